// round 5
// baseline (speedup 1.0000x reference)
#include <cuda_runtime.h>
#include <cuda_bf16.h>

// BBAStar: 8-connected grid shortest path, B=128, 32x32.
// R4: concurrent dual-orientation Gauss-Seidel. 512 threads/CTA:
//   warps 0-7  : V bands (warp owns 4 rows, lane = column)
//   warps 8-15 : H bands (warp owns 4 cols, lane = row)
// Both orientations sweep the SAME smem dist array concurrently; write-through
// is atomicMin on the int alias (positive floats: IEEE order == int order), so
// cells are monotone-decreasing and racy stale-high registers cannot corrupt.
// Every written value is a valid float path cost => converges to the exact
// fixed point of the reference's 1024 Jacobi sweeps. Zero-change epoch behind
// barriers => smem untouched and full operator applied => true fixed point.
// Backtrack via precomputed argmin directions (OFFS first-occurrence tie-break).

#define BN 128
#define ST 35              // smem row stride (odd => conflict-free both axes)
#define INF_F 1000000000.0f
#define EPS_F 1e-6f
#define KP 2               // fwd+bwd sweep pairs per epoch

__device__ __forceinline__ float shl(float v, int lane) {
    float t = __shfl_up_sync(0xffffffffu, v, 1);
    return (lane == 0) ? INF_F : t;
}
__device__ __forceinline__ float shr(float v, int lane) {
    float t = __shfl_down_sync(0xffffffffu, v, 1);
    return (lane == 31) ? INF_F : t;
}
__device__ __forceinline__ float min8f(float a, float b, float c, float d,
                                       float e, float f, float g, float h) {
    return fminf(fminf(fminf(a, b), fminf(c, d)),
                 fminf(fminf(e, f), fminf(g, h)));
}
__device__ __forceinline__ int pick8(float a0, float a1, float a2, float a3,
                                     float a4, float a5, float a6, float a7) {
    float bb = a0; int bd = 0;
    if (a1 < bb) { bb = a1; bd = 1; }
    if (a2 < bb) { bb = a2; bd = 2; }
    if (a3 < bb) { bb = a3; bd = 3; }
    if (a4 < bb) { bb = a4; bd = 4; }
    if (a5 < bb) { bb = a5; bd = 5; }
    if (a6 < bb) { bb = a6; bd = 6; }
    if (a7 < bb) { bb = a7; bd = 7; }
    return bd;
}

// One GS fwd+bwd sweep pair over 4 owned cells per lane.
// Own cell k at vd[i0 + k*di]; "prev" boundary at vd[ix], "next" at vd[iy].
// Diagonal-inclusive GS: freshly updated line is shfl'd before the next line.
// Writes go through atomicMin (monotone smem under dual ownership).
__device__ __forceinline__ void sweep_pair(volatile float* vd, int* id,
                                           const float w[4], float d[4],
                                           int i0, int di, int ix, int iy,
                                           int lane, bool& any)
{
    // forward sweep
    {
        float X = vd[ix], Y = vd[iy];
        float p = X, pl = shl(X, lane), pr = shr(X, lane);
        #pragma unroll
        for (int i = 0; i < 4; ++i) {
            float nx = (i < 3) ? d[i + 1] : Y;
            float nl = shl(nx, lane),  nr = shr(nx, lane);
            float cl = shl(d[i], lane), cr = shr(d[i], lane);
            float v = w[i] + min8f(pl, p, pr, cl, cr, nl, nx, nr);
            if (v < d[i]) {
                d[i] = v;
                atomicMin(&id[i0 + i * di], __float_as_int(v));
                any = true;
            }
            p = d[i]; pl = shl(p, lane); pr = shr(p, lane);
        }
    }
    // backward sweep
    {
        float X = vd[ix], Y = vd[iy];
        float p = Y, pl = shl(Y, lane), pr = shr(Y, lane);
        #pragma unroll
        for (int i = 3; i >= 0; --i) {
            float nx = (i > 0) ? d[i - 1] : X;
            float nl = shl(nx, lane),  nr = shr(nx, lane);
            float cl = shl(d[i], lane), cr = shr(d[i], lane);
            float v = w[i] + min8f(nl, nx, nr, cl, cr, pl, p, pr);
            if (v < d[i]) {
                d[i] = v;
                atomicMin(&id[i0 + i * di], __float_as_int(v));
                any = true;
            }
            p = d[i]; pl = shl(p, lane); pr = shr(p, lane);
        }
    }
}

__global__ void __launch_bounds__(512, 1)
bba_kernel(const float* __restrict__ weights,
           const int*   __restrict__ source,
           const int*   __restrict__ target,
           float*       __restrict__ out)
{
    __shared__ float dist[34 * ST];     // padded 34x34, stride 35
    __shared__ float wsh[32][33];       // weights, conflict-free both axes
    __shared__ int   nbr[1024];
    __shared__ int   changed;
    volatile float* vd = dist;
    int* id = (int*)dist;

    const int b    = blockIdx.x;
    const int tid  = threadIdx.x;
    const int wpid = tid >> 5;          // 0..15
    const int lane = tid & 31;
    const bool isV = (wpid < 8);
    const int band = isV ? wpid : (wpid - 8);
    const int g0   = 4 * band;          // first row (V) or col (H) of band

    // Zero poisoned output slice.
    out[b * 1024 + tid]       = 0.0f;
    out[b * 1024 + 512 + tid] = 0.0f;

    for (int i = tid; i < 34 * ST; i += 512) dist[i] = INF_F;
    if (tid == 0) changed = 0;

    // Weights (+EPS). V warps load row-major and stash for H warps.
    const float* wb = weights + b * 1024;
    float wreg[4];
    if (isV) {
        #pragma unroll
        for (int i = 0; i < 4; ++i) {
            wreg[i] = wb[(g0 + i) * 32 + lane] + EPS_F;
            wsh[g0 + i][lane] = wreg[i];
        }
    }

    const int sr = source[2 * b + 0];
    const int sc = source[2 * b + 1];
    const int tr = target[2 * b + 0];
    const int tc = target[2 * b + 1];

    __syncthreads();

    if (!isV) {
        #pragma unroll
        for (int i = 0; i < 4; ++i) wreg[i] = wsh[lane][g0 + i];
    }
    if (tid == 0) dist[(sr + 1) * ST + (sc + 1)] = wsh[sr][sc];
    __syncthreads();

    // Own-orientation indices.
    const int di = isV ? ST : 1;                                  // cell step
    const int i0 = isV ? ((g0 + 1) * ST + (lane + 1))             // first own cell
                       : ((lane + 1) * ST + (g0 + 1));
    const int ix = isV ? ((g0 + 0) * ST + (lane + 1))             // prev boundary
                       : ((lane + 1) * ST + (g0 + 0));
    const int iy = isV ? ((g0 + 5) * ST + (lane + 1))             // next boundary
                       : ((lane + 1) * ST + (g0 + 5));

    float d[4];

    for (;;) {
        bool any = false;

        // Refresh registers from smem, then KP racy GS sweep pairs.
        #pragma unroll
        for (int i = 0; i < 4; ++i) d[i] = vd[i0 + i * di];
        #pragma unroll 1
        for (int k = 0; k < KP; ++k)
            sweep_pair(vd, id, wreg, d, i0, di, ix, iy, lane, any);

        if (any) changed = 1;            // benign race
        __syncthreads();                 // epoch writes + flag visible
        int cf = changed;
        __syncthreads();                 // reads done before reset
        if (!cf) break;                  // zero-change epoch => fixed point
        if (tid == 0) changed = 0;
        __syncthreads();
    }

    // Parallel argmin-neighbor directions (V warps, V layout), OFFS order:
    // (-1,-1),(-1,0),(-1,1),(0,-1),(0,1),(1,-1),(1,0),(1,1)
    if (isV) {
        #pragma unroll
        for (int i = 0; i < 4; ++i) d[i] = vd[i0 + i * ST];
        float X  = vd[ix], Y = vd[iy];
        float XL = shl(X, lane),    XR = shr(X, lane);
        float L0 = shl(d[0], lane), R0 = shr(d[0], lane);
        float L1 = shl(d[1], lane), R1 = shr(d[1], lane);
        float L2 = shl(d[2], lane), R2 = shr(d[2], lane);
        float L3 = shl(d[3], lane), R3 = shr(d[3], lane);
        float YL = shl(Y, lane),    YR = shr(Y, lane);
        nbr[(g0 + 0) * 32 + lane] = pick8(XL, X,    XR, L0, R0, L1, d[1], R1);
        nbr[(g0 + 1) * 32 + lane] = pick8(L0, d[0], R0, L1, R1, L2, d[2], R2);
        nbr[(g0 + 2) * 32 + lane] = pick8(L1, d[1], R1, L2, R2, L3, d[3], R3);
        nbr[(g0 + 3) * 32 + lane] = pick8(L2, d[2], R2, L3, R3, YL, Y,    YR);
    }
    __syncthreads();

    // Serial backtrack: follow precomputed directions.
    if (tid == 0) {
        const int drs[8] = {-1, -1, -1,  0, 0,  1, 1, 1};
        const int dcs[8] = {-1,  0,  1, -1, 1, -1, 0, 1};
        int cr = tr, cc = tc;
        float* o = out + b * 1024;
        for (int step = 0; step < 1024; ++step) {
            o[cr * 32 + cc] = 1.0f;
            if (cr == sr && cc == sc) break;
            int k = nbr[cr * 32 + cc];
            cr += drs[k];
            cc += dcs[k];
        }
    }
}

extern "C" void kernel_launch(void* const* d_in, const int* in_sizes, int n_in,
                              void* d_out, int out_size)
{
    const float* weights = (const float*)d_in[0];
    const int*   source  = (const int*)d_in[1];
    const int*   target  = (const int*)d_in[2];
    float*       out     = (float*)d_out;

    bba_kernel<<<BN, 512>>>(weights, source, target, out);
}

// round 6
// speedup vs baseline: 1.1352x; 1.1352x over previous
#include <cuda_runtime.h>
#include <cuda_bf16.h>

// BBAStar: 8-connected grid shortest path, B=128, 32x32.
// R5: R3 structure (alternating V/H Gauss-Seidel phases, single owner per
// phase, write-through smem) with the per-epoch critical path slimmed:
//   - one fwd+bwd sweep pair per phase (KP=1)
//   - __syncthreads_or convergence flag (1 barrier instead of 3)
//   - shfl reuse: current-row shfls inherited from previous row's next-shfls
// Monotone relaxation => bit-exact float fixed point of the reference's 1024
// Jacobi sweeps, any schedule. Zero-change epoch => fixed point. Backtrack via
// precomputed argmin directions (exact OFFS first-occurrence tie-break).

#define BN 128
#define ST 35              // smem row stride (odd => conflict-free both axes)
#define INF_F 1000000000.0f
#define EPS_F 1e-6f

__device__ __forceinline__ float shl(float v, int lane) {
    float t = __shfl_up_sync(0xffffffffu, v, 1);
    return (lane == 0) ? INF_F : t;
}
__device__ __forceinline__ float shr(float v, int lane) {
    float t = __shfl_down_sync(0xffffffffu, v, 1);
    return (lane == 31) ? INF_F : t;
}
__device__ __forceinline__ float min8f(float a, float b, float c, float d,
                                       float e, float f, float g, float h) {
    return fminf(fminf(fminf(a, b), fminf(c, d)),
                 fminf(fminf(e, f), fminf(g, h)));
}
__device__ __forceinline__ int pick8(float a0, float a1, float a2, float a3,
                                     float a4, float a5, float a6, float a7) {
    float bb = a0; int bd = 0;
    if (a1 < bb) { bb = a1; bd = 1; }
    if (a2 < bb) { bb = a2; bd = 2; }
    if (a3 < bb) { bb = a3; bd = 3; }
    if (a4 < bb) { bb = a4; bd = 4; }
    if (a5 < bb) { bb = a5; bd = 5; }
    if (a6 < bb) { bb = a6; bd = 6; }
    if (a7 < bb) { bb = a7; bd = 7; }
    return bd;
}

// Forward GS sweep over the 4 owned lines. Fresh prev-line shfl (diagonal
// GS); current-line shfls reused from previous iteration's next-line shfls.
__device__ __forceinline__ void sweep_fwd(volatile float* vd, const float w[4],
                                          float d[4], int i0, int di,
                                          int ix, int iy, int lane, bool& any)
{
    float X = vd[ix], Y = vd[iy];
    float p = X, pl = shl(X, lane), pr = shr(X, lane);
    float cl = shl(d[0], lane), cr = shr(d[0], lane);
    #pragma unroll
    for (int i = 0; i < 4; ++i) {
        float nx = (i < 3) ? d[i + 1] : Y;
        float nl = shl(nx, lane), nr = shr(nx, lane);
        float v = w[i] + min8f(pl, p, pr, cl, cr, nl, nx, nr);
        if (v < d[i]) { d[i] = v; vd[i0 + i * di] = v; any = true; }
        p = d[i]; pl = shl(p, lane); pr = shr(p, lane);
        cl = nl; cr = nr;
    }
}
// Backward GS sweep (mirror).
__device__ __forceinline__ void sweep_bwd(volatile float* vd, const float w[4],
                                          float d[4], int i0, int di,
                                          int ix, int iy, int lane, bool& any)
{
    float X = vd[ix], Y = vd[iy];
    float p = Y, pl = shl(Y, lane), pr = shr(Y, lane);
    float cl = shl(d[3], lane), cr = shr(d[3], lane);
    #pragma unroll
    for (int i = 3; i >= 0; --i) {
        float nx = (i > 0) ? d[i - 1] : X;
        float nl = shl(nx, lane), nr = shr(nx, lane);
        float v = w[i] + min8f(nl, nx, nr, cl, cr, pl, p, pr);
        if (v < d[i]) { d[i] = v; vd[i0 + i * di] = v; any = true; }
        p = d[i]; pl = shl(p, lane); pr = shr(p, lane);
        cl = nl; cr = nr;
    }
}

__global__ void __launch_bounds__(256, 1)
bba_kernel(const float* __restrict__ weights,
           const int*   __restrict__ source,
           const int*   __restrict__ target,
           float*       __restrict__ out)
{
    __shared__ float dist[34 * ST];     // padded 34x34, stride 35
    __shared__ float wsh[32][33];       // weights, conflict-free both axes
    __shared__ int   nbr[1024];
    volatile float* vd = dist;

    const int b    = blockIdx.x;
    const int tid  = threadIdx.x;
    const int wpid = tid >> 5;          // warp id 0..7
    const int lane = tid & 31;
    const int r0   = 4 * wpid;          // V band first row
    const int c0   = 4 * wpid;          // H band first col

    // Zero poisoned output slice.
    #pragma unroll
    for (int i = 0; i < 4; ++i) out[b * 1024 + i * 256 + tid] = 0.0f;

    for (int i = tid; i < 34 * ST; i += 256) dist[i] = INF_F;

    // Weights (+EPS), V layout; stash for H-layout reads.
    const float* wb = weights + b * 1024;
    float wv[4], wh[4];
    #pragma unroll
    for (int i = 0; i < 4; ++i) {
        wv[i] = wb[(r0 + i) * 32 + lane] + EPS_F;
        wsh[r0 + i][lane] = wv[i];
    }

    const int sr = source[2 * b + 0];
    const int sc = source[2 * b + 1];
    const int tr = target[2 * b + 0];
    const int tc = target[2 * b + 1];

    __syncthreads();

    #pragma unroll
    for (int i = 0; i < 4; ++i) wh[i] = wsh[lane][c0 + i];
    if (tid == 0) dist[(sr + 1) * ST + (sc + 1)] = wsh[sr][sc];
    __syncthreads();

    const int v_i0 = (r0 + 1) * ST + (lane + 1);
    const int v_ix = (r0 + 0) * ST + (lane + 1);
    const int v_iy = (r0 + 5) * ST + (lane + 1);
    const int h_i0 = (lane + 1) * ST + (c0 + 1);
    const int h_ix = (lane + 1) * ST + (c0 + 0);
    const int h_iy = (lane + 1) * ST + (c0 + 5);

    float d[4];

    for (;;) {
        bool any = false;

        // V phase: reload own rows, fwd+bwd GS sweep.
        #pragma unroll
        for (int i = 0; i < 4; ++i) d[i] = vd[v_i0 + i * ST];
        sweep_fwd(vd, wv, d, v_i0, ST, v_ix, v_iy, lane, any);
        sweep_bwd(vd, wv, d, v_i0, ST, v_ix, v_iy, lane, any);

        __syncthreads();                 // V writes visible to H phase

        // H phase: reload own cols, fwd+bwd GS sweep.
        #pragma unroll
        for (int i = 0; i < 4; ++i) d[i] = vd[h_i0 + i];
        sweep_fwd(vd, wh, d, h_i0, 1, h_ix, h_iy, lane, any);
        sweep_bwd(vd, wh, d, h_i0, 1, h_ix, h_iy, lane, any);

        if (!__syncthreads_or((int)any)) break;   // zero-change epoch => fixed point
    }

    // Parallel argmin-neighbor directions (V layout), OFFS order:
    // (-1,-1),(-1,0),(-1,1),(0,-1),(0,1),(1,-1),(1,0),(1,1)
    {
        #pragma unroll
        for (int i = 0; i < 4; ++i) d[i] = vd[v_i0 + i * ST];
        float X  = vd[v_ix], Y = vd[v_iy];
        float XL = shl(X, lane),    XR = shr(X, lane);
        float L0 = shl(d[0], lane), R0 = shr(d[0], lane);
        float L1 = shl(d[1], lane), R1 = shr(d[1], lane);
        float L2 = shl(d[2], lane), R2 = shr(d[2], lane);
        float L3 = shl(d[3], lane), R3 = shr(d[3], lane);
        float YL = shl(Y, lane),    YR = shr(Y, lane);
        nbr[(r0 + 0) * 32 + lane] = pick8(XL, X,    XR, L0, R0, L1, d[1], R1);
        nbr[(r0 + 1) * 32 + lane] = pick8(L0, d[0], R0, L1, R1, L2, d[2], R2);
        nbr[(r0 + 2) * 32 + lane] = pick8(L1, d[1], R1, L2, R2, L3, d[3], R3);
        nbr[(r0 + 3) * 32 + lane] = pick8(L2, d[2], R2, L3, R3, YL, Y,    YR);
    }
    __syncthreads();

    // Serial backtrack: follow precomputed directions.
    if (tid == 0) {
        const int drs[8] = {-1, -1, -1,  0, 0,  1, 1, 1};
        const int dcs[8] = {-1,  0,  1, -1, 1, -1, 0, 1};
        int cr = tr, cc = tc;
        float* o = out + b * 1024;
        for (int step = 0; step < 1024; ++step) {
            o[cr * 32 + cc] = 1.0f;
            if (cr == sr && cc == sc) break;
            int k = nbr[cr * 32 + cc];
            cr += drs[k];
            cc += dcs[k];
        }
    }
}

extern "C" void kernel_launch(void* const* d_in, const int* in_sizes, int n_in,
                              void* d_out, int out_size)
{
    const float* weights = (const float*)d_in[0];
    const int*   source  = (const int*)d_in[1];
    const int*   target  = (const int*)d_in[2];
    float*       out     = (float*)d_out;

    bba_kernel<<<BN, 256>>>(weights, source, target, out);
}